// round 15
// baseline (speedup 1.0000x reference)
#include <cuda_runtime.h>
#include <cuda.h>
#include <cuda_bf16.h>
#include <math.h>
#include <math_constants.h>
#include <cstdint>

#define Bn  16
#define Cn  684
#define Hn  32
#define Wn  128
#define HIDn 256
#define An  512
#define HWn 4096
#define NTAP 121

// ---- scratch (device globals; no allocation allowed) ----
__device__ float    g_query[Bn * An];                      // [b][a]
__device__ __align__(1024) uint32_t g_weffb[An * 64];      // bf16x2 pairs: [a][tap-pair]
__device__ uint16_t g_X[(size_t)Bn * Hn * 128 * 136];      // im2col, padded rows (LDX=136)
__device__ float    g_epart[2 * Bn * HWn];                 // [half][b][pos]
__device__ float    g_alpha[Bn * HWn];
__device__ int      g_cnt[Bn];                             // per-batch completion counters

// k_energy SMEM layout (bytes) — TMA triple-buffered.  NO static shared in k_energy:
// dynamic base must stay 128-aligned for SW128 TMA destinations.
#define LDX 136
#define SM_X   0         // 34816
#define SM_W   34816     // 3 * 4096  (two SW128 sub-tiles of 2048 each)
#define SM_CF  47104     // 3 * 8192  (4 SW128 sub-tiles of 2048)
#define SM_CM  71680     // 3 * 8192  (SW64, 128 rows x 64B)
#define SM_QWA 96256     // 2048
#define SM_MB  98304     // 3 mbarriers (24B) + slast flag @ +24
#define SM_TOT 98368

#define STAGE_BYTES 20480u   // 4096 (W) + 8192 (CF) + 8192 (CM)

#define SWZ128(x) ((x) ^ (((x) >> 3) & 0x70))
#define SWZ64(x)  ((x) ^ (((x) >> 3) & 0x30))

__device__ __forceinline__ float fast_tanh(float x) {
    float y;
    asm("tanh.approx.f32 %0, %1;" : "=f"(y) : "f"(x));
    return y;
}
__device__ __forceinline__ uint32_t smem_u32(const void* p) {
    uint32_t a;
    asm("{ .reg .u64 t; cvta.to.shared.u64 t, %1; cvt.u32.u64 %0, t; }" : "=r"(a) : "l"(p));
    return a;
}
__device__ __forceinline__ void mbar_wait(uint32_t mb, uint32_t ph) {
    asm volatile(
        "{ .reg .pred P; \n"
        "W%=: mbarrier.try_wait.parity.acquire.cta.shared::cta.b64 P, [%0], %1, 0x989680;\n"
        "@P bra.uni D%=; bra.uni W%=; D%=: }"
        :: "r"(mb), "r"(ph) : "memory");
}

// ---------------- fused prep: query (0-15) + weff (16-143) + im2col (144-655) ----------------
#define WT_LD 124
__global__ void k_prep(const float* __restrict__ hidden,
                       const float* __restrict__ Wh,
                       const float* __restrict__ bh,
                       const float* __restrict__ Wattn,
                       const float* __restrict__ Wconv,
                       const float* __restrict__ asum) {
    __shared__ float sbuf[4 * 512 + 64 * WT_LD];   // 39.9 KB, shared by all branches
    const int tid = threadIdx.x;

    if (blockIdx.x == 0 && tid < Bn) g_cnt[tid] = 0;   // reset tail counters each replay

    if (blockIdx.x < 16) {
        // ---- query = hidden @ Wh^T + bh ----
        float* sh = sbuf;
        const int b = blockIdx.x;
        if (tid < HIDn) sh[tid] = hidden[b * HIDn + tid];
        __syncthreads();
        for (int a = tid; a < An; a += 256) {
            float s = bh[a];
            const float* w = Wh + (size_t)a * HIDn;
            #pragma unroll 8
            for (int k = 0; k < HIDn; k++) s = fmaf(w[k], sh[k], s);
            g_query[b * An + a] = s;
        }
    } else if (blockIdx.x < 144) {
        // ---- Weff[a][tap] = sum_k Wattn[a][k]*Wconv[k][tap], k-tiled SMEM ----
        float* sa = sbuf;                 // [4][512]
        float* wt = sbuf + 4 * 512;       // [64][WT_LD]
        const int chunk = blockIdx.x - 16;   // 0..127, 4 a-rows each
        for (int i = tid; i < 4 * 512; i += 256)
            sa[i] = Wattn[(size_t)chunk * 4 * 512 + i];

        const int al = tid >> 6, pr = tid & 63;
        const int t0 = pr * 2, t1 = pr * 2 + 1;
        float v0 = 0.f, v1 = 0.f;

        for (int kt = 0; kt < 8; kt++) {
            __syncthreads();
            for (int i = tid; i < 64 * NTAP; i += 256) {
                int r = i / NTAP, c = i % NTAP;
                wt[r * WT_LD + c] = Wconv[(size_t)(kt * 64 + r) * NTAP + c];
            }
            __syncthreads();
            if (t0 < NTAP) {
                #pragma unroll 8
                for (int k = 0; k < 64; k++)
                    v0 = fmaf(sa[al * 512 + kt * 64 + k], wt[k * WT_LD + t0], v0);
            }
            if (t1 < NTAP) {
                #pragma unroll 8
                for (int k = 0; k < 64; k++)
                    v1 = fmaf(sa[al * 512 + kt * 64 + k], wt[k * WT_LD + t1], v1);
            }
        }
        uint32_t lo = (uint32_t)__bfloat16_as_ushort(__float2bfloat16(v0));
        uint32_t hi = (uint32_t)__bfloat16_as_ushort(__float2bfloat16(v1));
        g_weffb[(chunk * 4 + al) * 64 + pr] = lo | (hi << 16);
    } else {
        // ---- im2col: X[b,h][128 pos][128 taps] bf16 (padded LDX) ----
        const int idx = blockIdx.x - 144;    // 0..511
        const int h = idx % Hn, b = idx / Hn;
        const float* arow = asum + (size_t)b * HWn;
        uint32_t* dst = (uint32_t*)(g_X + ((size_t)(b * Hn + h)) * 128 * LDX);
        for (int o = tid; o < 128 * 64; o += 256) {
            int mm = o >> 6, pr = o & 63;
            uint32_t packed = 0;
            #pragma unroll
            for (int hf = 0; hf < 2; hf++) {
                int k = pr * 2 + hf;
                float v = 0.f;
                if (k < NTAP) {
                    int i = k / 11, j = k % 11;
                    int gh = h - 5 + i, gw = mm - 5 + j;
                    if (gh >= 0 && gh < Hn && gw >= 0 && gw < Wn)
                        v = arow[gh * Wn + gw];
                }
                packed |= ((uint32_t)__bfloat16_as_ushort(__float2bfloat16(v))) << (16 * hf);
            }
            dst[mm * (LDX / 2) + pr] = packed;
        }
    }
}

// ---------------- energy: mma.sync + TMA-staged operands + softmax tail ----------------
// grid (2 a-halves, H, B), 256 threads (8 warps). Warp wid owns positions [16*wid, 16*wid+16).
__global__ void __launch_bounds__(256, 2) k_energy(
    const __grid_constant__ CUtensorMap tmCF,
    const __grid_constant__ CUtensorMap tmCM,
    const __grid_constant__ CUtensorMap tmW,
    const float* __restrict__ walpha,
    const float* __restrict__ asum,
    const int*   __restrict__ mask,
    float* __restrict__ out)
{
    extern __shared__ char smem[];
    const uint32_t sb = smem_u32(smem);
    const int half = blockIdx.x, h = blockIdx.y, b = blockIdx.z;
    const int tid = threadIdx.x, wid = tid >> 5, lane = tid & 31;
    const int g = lane >> 2, tig = lane & 3;

    // ---- stage X (plain copy) + QWA ----
    {
        const uint4* src = (const uint4*)(g_X + ((size_t)(b * Hn + h)) * 128 * LDX);
        uint4* dst = (uint4*)(smem + SM_X);
        #pragma unroll
        for (int o = tid; o < 2176; o += 256) dst[o] = src[o];
    }
    float2* QWA = (float2*)(smem + SM_QWA);
    QWA[tid] = make_float2(g_query[b * An + half * 256 + tid], walpha[half * 256 + tid]);

    if (tid == 0) {
        #pragma unroll
        for (int s = 0; s < 3; s++)
            asm volatile("mbarrier.init.shared.b64 [%0], %1;" :: "r"(sb + SM_MB + s * 8), "r"(1u) : "memory");
    }
    __syncthreads();

    // one-thread TMA stage of tile 'it' into buffer 'slot'
    auto stage = [&](int slot, int it) {
        const uint32_t mb = sb + SM_MB + slot * 8;
        const int a0 = half * 256 + it * 16;
        asm volatile("mbarrier.arrive.expect_tx.shared.b64 _, [%0], %1;" :: "r"(mb), "r"(STAGE_BYTES) : "memory");
        #pragma unroll
        for (int s = 0; s < 2; s++)
            asm volatile("cp.async.bulk.tensor.2d.shared::cta.global.tile.mbarrier::complete_tx::bytes "
                         "[%0], [%1, {%2, %3}], [%4];"
                         :: "r"(sb + SM_W + slot * 4096 + s * 2048), "l"(&tmW),
                            "r"(s * 32), "r"(a0), "r"(mb) : "memory");
        #pragma unroll
        for (int s = 0; s < 4; s++)
            asm volatile("cp.async.bulk.tensor.3d.shared::cta.global.tile.mbarrier::complete_tx::bytes "
                         "[%0], [%1, {%2, %3, %4}], [%5];"
                         :: "r"(sb + SM_CF + slot * 8192 + s * 2048), "l"(&tmCF),
                            "r"(s * 32), "r"(h), "r"(b * 512 + a0), "r"(mb) : "memory");
        asm volatile("cp.async.bulk.tensor.2d.shared::cta.global.tile.mbarrier::complete_tx::bytes "
                     "[%0], [%1, {%2, %3}], [%4];"
                     :: "r"(sb + SM_CM + slot * 8192), "l"(&tmCM),
                        "r"(a0), "r"((b * Hn + h) * 128), "r"(mb) : "memory");
    };

    if (tid == 0) { stage(0, 0); stage(1, 1); }

    // ---- persistent X fragments (both n-halves) ----
    const int pos0 = wid * 16;
    uint32_t bf[2][8][2];
    #pragma unroll
    for (int nh = 0; nh < 2; nh++) {
        const char* xrow = smem + SM_X + (pos0 + nh * 8 + g) * (LDX * 2);
        #pragma unroll
        for (int kk = 0; kk < 8; kk++) {
            bf[nh][kk][0] = *(const uint32_t*)(xrow + (kk * 16 + tig * 2) * 2);
            bf[nh][kk][1] = *(const uint32_t*)(xrow + (kk * 16 + tig * 2 + 8) * 2);
        }
    }

    float epos[4] = {0.f, 0.f, 0.f, 0.f};
    const int p0 = pos0 + tig * 2;
    const int st = p0 >> 5, pl = p0 & 31;

    #pragma unroll
    for (int mt = 0; mt < 16; mt++) {
        const int slot = mt % 3;
        const uint32_t ph = (uint32_t)((mt / 3) & 1);

        mbar_wait(sb + SM_MB + slot * 8, ph);
        __syncthreads();

        if (tid == 0 && mt < 14) stage((mt + 2) % 3, mt + 2);

        // ---- GEMM ----
        const uint32_t wb = sb + SM_W + slot * 4096;
        const uint32_t wlane = (uint32_t)((lane & 15) * 128 + (lane >> 4) * 16);
        float c0[4] = {0.f, 0.f, 0.f, 0.f};
        float c1[4] = {0.f, 0.f, 0.f, 0.f};
        #pragma unroll
        for (int kk = 0; kk < 8; kk++) {
            uint32_t a0r, a1r, a2r, a3r;
            uint32_t addr = wb + (kk >> 2) * 2048 + SWZ128(wlane + (kk & 3) * 32);
            asm volatile("ldmatrix.sync.aligned.m8n8.x4.shared.b16 {%0,%1,%2,%3}, [%4];"
                         : "=r"(a0r), "=r"(a1r), "=r"(a2r), "=r"(a3r) : "r"(addr));
            asm volatile("mma.sync.aligned.m16n8k16.row.col.f32.bf16.bf16.f32 "
                         "{%0,%1,%2,%3}, {%4,%5,%6,%7}, {%8,%9}, {%0,%1,%2,%3};"
                         : "+f"(c0[0]), "+f"(c0[1]), "+f"(c0[2]), "+f"(c0[3])
                         : "r"(a0r), "r"(a1r), "r"(a2r), "r"(a3r),
                           "r"(bf[0][kk][0]), "r"(bf[0][kk][1]));
            asm volatile("mma.sync.aligned.m16n8k16.row.col.f32.bf16.bf16.f32 "
                         "{%0,%1,%2,%3}, {%4,%5,%6,%7}, {%8,%9}, {%0,%1,%2,%3};"
                         : "+f"(c1[0]), "+f"(c1[1]), "+f"(c1[2]), "+f"(c1[3])
                         : "r"(a0r), "r"(a1r), "r"(a2r), "r"(a3r),
                           "r"(bf[1][kk][0]), "r"(bf[1][kk][1]));
        }

        // ---- epilogue ----
        const char* cfp = smem + SM_CF + slot * 8192 + st * 2048;
        const char* cmp = smem + SM_CM + slot * 8192;
        const int A0l = mt * 16;
        const float2 qw0 = QWA[A0l + g], qw1 = QWA[A0l + g + 8];

        float2 cf00 = *(const float2*)(cfp + SWZ128(g * 128 + pl * 4));
        float2 cf01 = *(const float2*)(cfp + SWZ128((g + 8) * 128 + pl * 4));
        float2 cf10 = *(const float2*)(cfp + SWZ128(g * 128 + (pl + 8) * 4));
        float2 cf11 = *(const float2*)(cfp + SWZ128((g + 8) * 128 + (pl + 8) * 4));

        float cm00a = *(const float*)(cmp + SWZ64(p0 * 64 + g * 4));
        float cm00b = *(const float*)(cmp + SWZ64((p0 + 1) * 64 + g * 4));
        float cm01a = *(const float*)(cmp + SWZ64(p0 * 64 + g * 4 + 32));
        float cm01b = *(const float*)(cmp + SWZ64((p0 + 1) * 64 + g * 4 + 32));
        float cm10a = *(const float*)(cmp + SWZ64((p0 + 8) * 64 + g * 4));
        float cm10b = *(const float*)(cmp + SWZ64((p0 + 9) * 64 + g * 4));
        float cm11a = *(const float*)(cmp + SWZ64((p0 + 8) * 64 + g * 4 + 32));
        float cm11b = *(const float*)(cmp + SWZ64((p0 + 9) * 64 + g * 4 + 32));

        float s;
        s = c0[0] + cf00.x + cm00a + qw0.x; epos[0] = fmaf(qw0.y, fast_tanh(s), epos[0]);
        s = c0[1] + cf00.y + cm00b + qw0.x; epos[1] = fmaf(qw0.y, fast_tanh(s), epos[1]);
        s = c0[2] + cf01.x + cm01a + qw1.x; epos[0] = fmaf(qw1.y, fast_tanh(s), epos[0]);
        s = c0[3] + cf01.y + cm01b + qw1.x; epos[1] = fmaf(qw1.y, fast_tanh(s), epos[1]);
        s = c1[0] + cf10.x + cm10a + qw0.x; epos[2] = fmaf(qw0.y, fast_tanh(s), epos[2]);
        s = c1[1] + cf10.y + cm10b + qw0.x; epos[3] = fmaf(qw0.y, fast_tanh(s), epos[3]);
        s = c1[2] + cf11.x + cm11a + qw1.x; epos[2] = fmaf(qw1.y, fast_tanh(s), epos[2]);
        s = c1[3] + cf11.y + cm11b + qw1.x; epos[3] = fmaf(qw1.y, fast_tanh(s), epos[3]);
    }

    // reduce over the 8 g-lanes (lane bits 2-4)
    #pragma unroll
    for (int j = 0; j < 4; j++) {
        epos[j] += __shfl_xor_sync(0xffffffffu, epos[j], 4);
        epos[j] += __shfl_xor_sync(0xffffffffu, epos[j], 8);
        epos[j] += __shfl_xor_sync(0xffffffffu, epos[j], 16);
    }
    if (lane < 4) {
        float* ep = g_epart + ((size_t)half * Bn + b) * HWn + h * Wn + pos0;
        ep[tig * 2]         = epos[0];
        ep[tig * 2 + 1]     = epos[1];
        ep[8 + tig * 2]     = epos[2];
        ep[8 + tig * 2 + 1] = epos[3];
    }

    // ---- softmax tail: last block per batch (threadFenceReduction pattern) ----
    // slast flag lives in DYNAMIC smem (no static shared -> TMA dsts stay 128-aligned)
    int* slastp = (int*)(smem + SM_MB + 24);
    __threadfence();
    __syncthreads();            // all epart stores issued before the arrival
    if (tid == 0) {
        int old = atomicAdd(&g_cnt[b], 1);
        *slastp = (old == 2 * Hn - 1);
    }
    __syncthreads();
    if (*slastp == 0) return;

    // this block: deterministic per-batch softmax over 4096 positions
    float* se  = (float*)smem;            // 16 KB (X region, no longer needed)
    float* red = (float*)(smem + 16384);  // 1 KB

    float mx = -CUDART_INF_F;
    #pragma unroll
    for (int i = 0; i < 16; i++) {
        int p = i * 256 + tid;
        float e = g_epart[b * HWn + p] + g_epart[(Bn + b) * HWn + p];
        if (mask[b * HWn + p] == 0) e = -CUDART_INF_F;
        se[p] = e;
        mx = fmaxf(mx, e);
    }
    red[tid] = mx; __syncthreads();
    for (int s = 128; s; s >>= 1) {
        if (tid < s) red[tid] = fmaxf(red[tid], red[tid + s]);
        __syncthreads();
    }
    mx = red[0]; __syncthreads();

    float sum = 0.f;
    #pragma unroll
    for (int i = 0; i < 16; i++) {
        int p = i * 256 + tid;
        float ex = __expf(se[p] - mx);
        se[p] = ex;
        sum += ex;
    }
    red[tid] = sum; __syncthreads();
    for (int s = 128; s; s >>= 1) {
        if (tid < s) red[tid] += red[tid + s];
        __syncthreads();
    }
    sum = red[0]; __syncthreads();

    const float inv = 1.f / sum;
    float* out_alpha = out + Bn * Cn;
    float* out_asum  = out + Bn * Cn + Bn * HWn;
    #pragma unroll
    for (int i = 0; i < 16; i++) {
        int p = i * 256 + tid;
        float al = se[p] * inv;
        g_alpha[b * HWn + p] = al;
        out_alpha[b * HWn + p] = al;
        out_asum[b * HWn + p] = al + asum[b * HWn + p];
    }
}

// ---------------- context ----------------
__global__ void k_context(const float* __restrict__ cnn,
                          float* __restrict__ out) {
    const int c = blockIdx.x, b = blockIdx.y, tid = threadIdx.x;
    const float4* row = (const float4*)(cnn + ((size_t)b * Cn + c) * HWn);
    const float4* al  = (const float4*)(g_alpha + b * HWn);
    float s = 0.f;
    #pragma unroll
    for (int it = 0; it < 4; it++) {
        int p = it * 256 + tid;
        float4 r = row[p], a = al[p];
        s = fmaf(a.x, r.x, s); s = fmaf(a.y, r.y, s);
        s = fmaf(a.z, r.z, s); s = fmaf(a.w, r.w, s);
    }
    #pragma unroll
    for (int off = 16; off; off >>= 1)
        s += __shfl_xor_sync(0xffffffffu, s, off);
    __shared__ float red[8];
    if ((tid & 31) == 0) red[tid >> 5] = s;
    __syncthreads();
    if (tid == 0) {
        float t = red[0] + red[1] + red[2] + red[3]
                + red[4] + red[5] + red[6] + red[7];
        out[b * Cn + c] = t;
    }
}

typedef CUresult (*PFN_encodeTiled)(
    CUtensorMap*, CUtensorMapDataType, cuuint32_t, void*,
    const cuuint64_t*, const cuuint64_t*, const cuuint32_t*, const cuuint32_t*,
    CUtensorMapInterleave, CUtensorMapSwizzle, CUtensorMapL2promotion, CUtensorMapFloatOOBfill);

extern "C" void kernel_launch(void* const* d_in, const int* in_sizes, int n_in,
                              void* d_out, int out_size) {
    const float* cnn     = (const float*)d_in[0];   // [16,684,32,128]
    const float* cft     = (const float*)d_in[1];   // [16,512,32,128]
    const float* hidden  = (const float*)d_in[2];   // [16,256]
    const float* asum    = (const float*)d_in[3];   // [16,1,32,128]
    const int*   mask    = (const int*)  d_in[4];   // [16,1,32,128]
    const float* cmt     = (const float*)d_in[5];   // [16,32,128,512]
    const float* Wh      = (const float*)d_in[6];   // [512,256]
    const float* bh      = (const float*)d_in[7];   // [512]
    const float* Wconv   = (const float*)d_in[8];   // [512,1,11,11]
    const float* Wattn   = (const float*)d_in[9];   // [512,512]
    const float* Walpha  = (const float*)d_in[10];  // [1,512]
    // d_in[11] = b_alpha: softmax-invariant, skipped

    float* out = (float*)d_out; // [ context 16*684 | alpha 16*4096 | alpha_sum_new 16*4096 ]

    // ---- build tensormaps (host CPU work at capture; no allocation) ----
    void* fn = nullptr;
    cudaDriverEntryPointQueryResult qr;
    cudaGetDriverEntryPoint("cuTensorMapEncodeTiled", &fn, cudaEnableDefault, &qr);
    PFN_encodeTiled enc = (PFN_encodeTiled)fn;

    void* wptr = nullptr;
    cudaGetSymbolAddress(&wptr, g_weffb);

    CUtensorMap tmCF, tmCM, tmW;
    {   // cft as [w=128][h=32][b*A=8192] f32, box {32,1,16}, SW128
        cuuint64_t d[3]  = {128, 32, 8192};
        cuuint64_t s[2]  = {512, 16384};
        cuuint32_t bx[3] = {32, 1, 16};
        cuuint32_t es[3] = {1, 1, 1};
        enc(&tmCF, CU_TENSOR_MAP_DATA_TYPE_FLOAT32, 3, (void*)cft, d, s, bx, es,
            CU_TENSOR_MAP_INTERLEAVE_NONE, CU_TENSOR_MAP_SWIZZLE_128B,
            CU_TENSOR_MAP_L2_PROMOTION_L2_128B, CU_TENSOR_MAP_FLOAT_OOB_FILL_NONE);
    }
    {   // cmt as [A=512][b*h*w=65536] f32, box {16,128}, SW64
        cuuint64_t d[2]  = {512, 65536};
        cuuint64_t s[1]  = {2048};
        cuuint32_t bx[2] = {16, 128};
        cuuint32_t es[2] = {1, 1};
        enc(&tmCM, CU_TENSOR_MAP_DATA_TYPE_FLOAT32, 2, (void*)cmt, d, s, bx, es,
            CU_TENSOR_MAP_INTERLEAVE_NONE, CU_TENSOR_MAP_SWIZZLE_64B,
            CU_TENSOR_MAP_L2_PROMOTION_L2_128B, CU_TENSOR_MAP_FLOAT_OOB_FILL_NONE);
    }
    {   // g_weffb as [64 u32][512 a], box {32,16}, SW128
        cuuint64_t d[2]  = {64, 512};
        cuuint64_t s[1]  = {256};
        cuuint32_t bx[2] = {32, 16};
        cuuint32_t es[2] = {1, 1};
        enc(&tmW, CU_TENSOR_MAP_DATA_TYPE_UINT32, 2, wptr, d, s, bx, es,
            CU_TENSOR_MAP_INTERLEAVE_NONE, CU_TENSOR_MAP_SWIZZLE_128B,
            CU_TENSOR_MAP_L2_PROMOTION_L2_128B, CU_TENSOR_MAP_FLOAT_OOB_FILL_NONE);
    }

    cudaFuncSetAttribute(k_energy, cudaFuncAttributeMaxDynamicSharedMemorySize, SM_TOT);

    k_prep<<<656, 256>>>(hidden, Wh, bh, Wattn, Wconv, asum);
    k_energy<<<dim3(2, Hn, Bn), 256, SM_TOT>>>(tmCF, tmCM, tmW, Walpha, asum, mask, out);
    k_context<<<dim3(Cn, Bn), 256>>>(cnn, out);
}

// round 16
// speedup vs baseline: 1.2053x; 1.2053x over previous
#include <cuda_runtime.h>
#include <cuda.h>
#include <cuda_bf16.h>
#include <math.h>
#include <math_constants.h>
#include <cstdint>

#define Bn  16
#define Cn  684
#define Hn  32
#define Wn  128
#define HIDn 256
#define An  512
#define HWn 4096
#define NTAP 121

// ---- scratch (device globals; no allocation allowed) ----
__device__ float    g_query[Bn * An];                      // [b][a]
__device__ __align__(1024) uint32_t g_weffb[An * 64];      // bf16x2 pairs: [a][tap-pair]
__device__ uint16_t g_X[(size_t)Bn * Hn * 128 * 136];      // im2col, padded rows (LDX=136)
__device__ float    g_epart[2 * Bn * HWn];                 // [half][b][pos]
__device__ float    g_alpha[Bn * HWn];
__device__ int      g_cnt[Bn];                             // per-batch completion counters

// k_energy SMEM layout (bytes) — TMA triple-buffered.  NO static shared in k_energy:
// dynamic base must stay 128-aligned for SW128 TMA destinations.
#define LDX 136
#define SM_X   0         // 34816
#define SM_W   34816     // 3 * 4096  (two SW128 sub-tiles of 2048 each)
#define SM_CF  47104     // 3 * 8192  (4 SW128 sub-tiles of 2048)
#define SM_CM  71680     // 3 * 8192  (SW64, 128 rows x 64B)
#define SM_QWA 96256     // 2048
#define SM_MB  98304     // 3 mbarriers (24B) + slast flag @ +24
#define SM_TOT 98368

#define STAGE_BYTES 20480u   // 4096 (W) + 8192 (CF) + 8192 (CM)

#define SWZ128(x) ((x) ^ (((x) >> 3) & 0x70))
#define SWZ64(x)  ((x) ^ (((x) >> 3) & 0x30))

__device__ __forceinline__ float fast_tanh(float x) {
    float y;
    asm("tanh.approx.f32 %0, %1;" : "=f"(y) : "f"(x));
    return y;
}
__device__ __forceinline__ uint32_t smem_u32(const void* p) {
    uint32_t a;
    asm("{ .reg .u64 t; cvta.to.shared.u64 t, %1; cvt.u32.u64 %0, t; }" : "=r"(a) : "l"(p));
    return a;
}
__device__ __forceinline__ void mbar_wait(uint32_t mb, uint32_t ph) {
    asm volatile(
        "{ .reg .pred P; \n"
        "W%=: mbarrier.try_wait.parity.acquire.cta.shared::cta.b64 P, [%0], %1, 0x989680;\n"
        "@P bra.uni D%=; bra.uni W%=; D%=: }"
        :: "r"(mb), "r"(ph) : "memory");
}

// ---------------- fused prep: query (0-15) + weff (16-143) + im2col (144-655) ----------------
// static SMEM kept at 8 KB so ALL branches run at high occupancy (R15 post-mortem).
__global__ void k_prep(const float* __restrict__ hidden,
                       const float* __restrict__ Wh,
                       const float* __restrict__ bh,
                       const float* __restrict__ Wattn,
                       const float* __restrict__ Wconv,
                       const float* __restrict__ asum) {
    __shared__ float sbuf[2048];   // 8 KB, shared by all branches
    const int tid = threadIdx.x;

    if (blockIdx.x == 0 && tid < Bn) g_cnt[tid] = 0;   // reset tail counters each replay

    if (blockIdx.x < 16) {
        // ---- query = hidden @ Wh^T + bh ----
        const int b = blockIdx.x;
        if (tid < HIDn) sbuf[tid] = hidden[b * HIDn + tid];
        __syncthreads();
        for (int a = tid; a < An; a += 256) {
            float s = bh[a];
            const float* w = Wh + (size_t)a * HIDn;
            #pragma unroll 8
            for (int k = 0; k < HIDn; k++) s = fmaf(w[k], sbuf[k], s);
            g_query[b * An + a] = s;
        }
    } else if (blockIdx.x < 144) {
        // ---- Weff[a][tap] = sum_k Wattn[a][k]*Wconv[k][tap] -> bf16 pairs (R13 version) ----
        const int chunk = blockIdx.x - 16;   // 0..127, 4 a-rows each
        for (int i = tid; i < 4 * 512; i += 256)
            sbuf[i] = Wattn[(size_t)chunk * 4 * 512 + i];
        __syncthreads();
        const int al = tid >> 6, pr = tid & 63;
        float v0 = 0.f, v1 = 0.f;
        const int t0 = pr * 2, t1 = pr * 2 + 1;
        if (t0 < NTAP) {
            #pragma unroll 8
            for (int k = 0; k < 512; k++)
                v0 = fmaf(sbuf[al * 512 + k], __ldg(&Wconv[(size_t)k * NTAP + t0]), v0);
        }
        if (t1 < NTAP) {
            #pragma unroll 8
            for (int k = 0; k < 512; k++)
                v1 = fmaf(sbuf[al * 512 + k], __ldg(&Wconv[(size_t)k * NTAP + t1]), v1);
        }
        uint32_t lo = (uint32_t)__bfloat16_as_ushort(__float2bfloat16(v0));
        uint32_t hi = (uint32_t)__bfloat16_as_ushort(__float2bfloat16(v1));
        g_weffb[(chunk * 4 + al) * 64 + pr] = lo | (hi << 16);
    } else {
        // ---- im2col via SMEM halo window (coalesced loads, LDS-fed taps) ----
        const int idx = blockIdx.x - 144;    // 0..511
        const int h = idx % Hn, b = idx / Hn;
        const float* arow = asum + (size_t)b * HWn;
        float (*win)[144] = (float(*)[144])sbuf;   // 11 x 144 = 1584 floats

        for (int i = tid; i < 11 * 144; i += 256) {
            int r = i / 144, c = i % 144;
            int gh = h - 5 + r, gw = c - 5;
            float v = 0.f;
            if (gh >= 0 && gh < Hn && gw >= 0 && gw < Wn)
                v = arow[gh * Wn + gw];
            win[r][c] = v;
        }
        __syncthreads();

        uint32_t* dst = (uint32_t*)(g_X + ((size_t)(b * Hn + h)) * 128 * LDX);
        for (int o = tid; o < 128 * 64; o += 256) {
            int mm = o >> 6, pr = o & 63;
            uint32_t packed = 0;
            #pragma unroll
            for (int hf = 0; hf < 2; hf++) {
                int k = pr * 2 + hf;
                float v = 0.f;
                if (k < NTAP) {
                    int i = k / 11, j = k % 11;
                    v = win[i][mm + j];
                }
                packed |= ((uint32_t)__bfloat16_as_ushort(__float2bfloat16(v))) << (16 * hf);
            }
            dst[mm * (LDX / 2) + pr] = packed;
        }
    }
}

// ---------------- energy: mma.sync + TMA-staged operands + softmax tail ----------------
// grid (2 a-halves, H, B), 256 threads (8 warps). Warp wid owns positions [16*wid, 16*wid+16).
__global__ void __launch_bounds__(256, 2) k_energy(
    const __grid_constant__ CUtensorMap tmCF,
    const __grid_constant__ CUtensorMap tmCM,
    const __grid_constant__ CUtensorMap tmW,
    const float* __restrict__ walpha,
    const float* __restrict__ asum,
    const int*   __restrict__ mask,
    float* __restrict__ out)
{
    extern __shared__ char smem[];
    const uint32_t sb = smem_u32(smem);
    const int half = blockIdx.x, h = blockIdx.y, b = blockIdx.z;
    const int tid = threadIdx.x, wid = tid >> 5, lane = tid & 31;
    const int g = lane >> 2, tig = lane & 3;

    // ---- stage X (plain copy) + QWA ----
    {
        const uint4* src = (const uint4*)(g_X + ((size_t)(b * Hn + h)) * 128 * LDX);
        uint4* dst = (uint4*)(smem + SM_X);
        #pragma unroll
        for (int o = tid; o < 2176; o += 256) dst[o] = src[o];
    }
    float2* QWA = (float2*)(smem + SM_QWA);
    QWA[tid] = make_float2(g_query[b * An + half * 256 + tid], walpha[half * 256 + tid]);

    if (tid == 0) {
        #pragma unroll
        for (int s = 0; s < 3; s++)
            asm volatile("mbarrier.init.shared.b64 [%0], %1;" :: "r"(sb + SM_MB + s * 8), "r"(1u) : "memory");
    }
    __syncthreads();

    // one-thread TMA stage of tile 'it' into buffer 'slot'
    auto stage = [&](int slot, int it) {
        const uint32_t mb = sb + SM_MB + slot * 8;
        const int a0 = half * 256 + it * 16;
        asm volatile("mbarrier.arrive.expect_tx.shared.b64 _, [%0], %1;" :: "r"(mb), "r"(STAGE_BYTES) : "memory");
        #pragma unroll
        for (int s = 0; s < 2; s++)
            asm volatile("cp.async.bulk.tensor.2d.shared::cta.global.tile.mbarrier::complete_tx::bytes "
                         "[%0], [%1, {%2, %3}], [%4];"
                         :: "r"(sb + SM_W + slot * 4096 + s * 2048), "l"(&tmW),
                            "r"(s * 32), "r"(a0), "r"(mb) : "memory");
        #pragma unroll
        for (int s = 0; s < 4; s++)
            asm volatile("cp.async.bulk.tensor.3d.shared::cta.global.tile.mbarrier::complete_tx::bytes "
                         "[%0], [%1, {%2, %3, %4}], [%5];"
                         :: "r"(sb + SM_CF + slot * 8192 + s * 2048), "l"(&tmCF),
                            "r"(s * 32), "r"(h), "r"(b * 512 + a0), "r"(mb) : "memory");
        asm volatile("cp.async.bulk.tensor.2d.shared::cta.global.tile.mbarrier::complete_tx::bytes "
                     "[%0], [%1, {%2, %3}], [%4];"
                     :: "r"(sb + SM_CM + slot * 8192), "l"(&tmCM),
                        "r"(a0), "r"((b * Hn + h) * 128), "r"(mb) : "memory");
    };

    if (tid == 0) { stage(0, 0); stage(1, 1); }

    // ---- persistent X fragments (both n-halves) ----
    const int pos0 = wid * 16;
    uint32_t bf[2][8][2];
    #pragma unroll
    for (int nh = 0; nh < 2; nh++) {
        const char* xrow = smem + SM_X + (pos0 + nh * 8 + g) * (LDX * 2);
        #pragma unroll
        for (int kk = 0; kk < 8; kk++) {
            bf[nh][kk][0] = *(const uint32_t*)(xrow + (kk * 16 + tig * 2) * 2);
            bf[nh][kk][1] = *(const uint32_t*)(xrow + (kk * 16 + tig * 2 + 8) * 2);
        }
    }

    float epos[4] = {0.f, 0.f, 0.f, 0.f};
    const int p0 = pos0 + tig * 2;
    const int st = p0 >> 5, pl = p0 & 31;

    #pragma unroll
    for (int mt = 0; mt < 16; mt++) {
        const int slot = mt % 3;
        const uint32_t ph = (uint32_t)((mt / 3) & 1);

        mbar_wait(sb + SM_MB + slot * 8, ph);
        __syncthreads();

        if (tid == 0 && mt < 14) stage((mt + 2) % 3, mt + 2);

        // ---- GEMM ----
        const uint32_t wb = sb + SM_W + slot * 4096;
        const uint32_t wlane = (uint32_t)((lane & 15) * 128 + (lane >> 4) * 16);
        float c0[4] = {0.f, 0.f, 0.f, 0.f};
        float c1[4] = {0.f, 0.f, 0.f, 0.f};
        #pragma unroll
        for (int kk = 0; kk < 8; kk++) {
            uint32_t a0r, a1r, a2r, a3r;
            uint32_t addr = wb + (kk >> 2) * 2048 + SWZ128(wlane + (kk & 3) * 32);
            asm volatile("ldmatrix.sync.aligned.m8n8.x4.shared.b16 {%0,%1,%2,%3}, [%4];"
                         : "=r"(a0r), "=r"(a1r), "=r"(a2r), "=r"(a3r) : "r"(addr));
            asm volatile("mma.sync.aligned.m16n8k16.row.col.f32.bf16.bf16.f32 "
                         "{%0,%1,%2,%3}, {%4,%5,%6,%7}, {%8,%9}, {%0,%1,%2,%3};"
                         : "+f"(c0[0]), "+f"(c0[1]), "+f"(c0[2]), "+f"(c0[3])
                         : "r"(a0r), "r"(a1r), "r"(a2r), "r"(a3r),
                           "r"(bf[0][kk][0]), "r"(bf[0][kk][1]));
            asm volatile("mma.sync.aligned.m16n8k16.row.col.f32.bf16.bf16.f32 "
                         "{%0,%1,%2,%3}, {%4,%5,%6,%7}, {%8,%9}, {%0,%1,%2,%3};"
                         : "+f"(c1[0]), "+f"(c1[1]), "+f"(c1[2]), "+f"(c1[3])
                         : "r"(a0r), "r"(a1r), "r"(a2r), "r"(a3r),
                           "r"(bf[1][kk][0]), "r"(bf[1][kk][1]));
        }

        // ---- epilogue ----
        const char* cfp = smem + SM_CF + slot * 8192 + st * 2048;
        const char* cmp = smem + SM_CM + slot * 8192;
        const int A0l = mt * 16;
        const float2 qw0 = QWA[A0l + g], qw1 = QWA[A0l + g + 8];

        float2 cf00 = *(const float2*)(cfp + SWZ128(g * 128 + pl * 4));
        float2 cf01 = *(const float2*)(cfp + SWZ128((g + 8) * 128 + pl * 4));
        float2 cf10 = *(const float2*)(cfp + SWZ128(g * 128 + (pl + 8) * 4));
        float2 cf11 = *(const float2*)(cfp + SWZ128((g + 8) * 128 + (pl + 8) * 4));

        float cm00a = *(const float*)(cmp + SWZ64(p0 * 64 + g * 4));
        float cm00b = *(const float*)(cmp + SWZ64((p0 + 1) * 64 + g * 4));
        float cm01a = *(const float*)(cmp + SWZ64(p0 * 64 + g * 4 + 32));
        float cm01b = *(const float*)(cmp + SWZ64((p0 + 1) * 64 + g * 4 + 32));
        float cm10a = *(const float*)(cmp + SWZ64((p0 + 8) * 64 + g * 4));
        float cm10b = *(const float*)(cmp + SWZ64((p0 + 9) * 64 + g * 4));
        float cm11a = *(const float*)(cmp + SWZ64((p0 + 8) * 64 + g * 4 + 32));
        float cm11b = *(const float*)(cmp + SWZ64((p0 + 9) * 64 + g * 4 + 32));

        float s;
        s = c0[0] + cf00.x + cm00a + qw0.x; epos[0] = fmaf(qw0.y, fast_tanh(s), epos[0]);
        s = c0[1] + cf00.y + cm00b + qw0.x; epos[1] = fmaf(qw0.y, fast_tanh(s), epos[1]);
        s = c0[2] + cf01.x + cm01a + qw1.x; epos[0] = fmaf(qw1.y, fast_tanh(s), epos[0]);
        s = c0[3] + cf01.y + cm01b + qw1.x; epos[1] = fmaf(qw1.y, fast_tanh(s), epos[1]);
        s = c1[0] + cf10.x + cm10a + qw0.x; epos[2] = fmaf(qw0.y, fast_tanh(s), epos[2]);
        s = c1[1] + cf10.y + cm10b + qw0.x; epos[3] = fmaf(qw0.y, fast_tanh(s), epos[3]);
        s = c1[2] + cf11.x + cm11a + qw1.x; epos[2] = fmaf(qw1.y, fast_tanh(s), epos[2]);
        s = c1[3] + cf11.y + cm11b + qw1.x; epos[3] = fmaf(qw1.y, fast_tanh(s), epos[3]);
    }

    // reduce over the 8 g-lanes (lane bits 2-4)
    #pragma unroll
    for (int j = 0; j < 4; j++) {
        epos[j] += __shfl_xor_sync(0xffffffffu, epos[j], 4);
        epos[j] += __shfl_xor_sync(0xffffffffu, epos[j], 8);
        epos[j] += __shfl_xor_sync(0xffffffffu, epos[j], 16);
    }
    if (lane < 4) {
        float* ep = g_epart + ((size_t)half * Bn + b) * HWn + h * Wn + pos0;
        ep[tig * 2]         = epos[0];
        ep[tig * 2 + 1]     = epos[1];
        ep[8 + tig * 2]     = epos[2];
        ep[8 + tig * 2 + 1] = epos[3];
    }

    // ---- softmax tail: last block per batch (threadFenceReduction pattern) ----
    // slast flag lives in DYNAMIC smem (no static shared -> TMA dsts stay 128-aligned)
    int* slastp = (int*)(smem + SM_MB + 24);
    __threadfence();
    __syncthreads();            // all epart stores issued before the arrival
    if (tid == 0) {
        int old = atomicAdd(&g_cnt[b], 1);
        *slastp = (old == 2 * Hn - 1);
    }
    __syncthreads();
    if (*slastp == 0) return;

    // this block: deterministic per-batch softmax over 4096 positions
    float* se  = (float*)smem;            // 16 KB (X region, no longer needed)
    float* red = (float*)(smem + 16384);  // 1 KB

    float mx = -CUDART_INF_F;
    #pragma unroll
    for (int i = 0; i < 16; i++) {
        int p = i * 256 + tid;
        float e = g_epart[b * HWn + p] + g_epart[(Bn + b) * HWn + p];
        if (mask[b * HWn + p] == 0) e = -CUDART_INF_F;
        se[p] = e;
        mx = fmaxf(mx, e);
    }
    red[tid] = mx; __syncthreads();
    for (int s = 128; s; s >>= 1) {
        if (tid < s) red[tid] = fmaxf(red[tid], red[tid + s]);
        __syncthreads();
    }
    mx = red[0]; __syncthreads();

    float sum = 0.f;
    #pragma unroll
    for (int i = 0; i < 16; i++) {
        int p = i * 256 + tid;
        float ex = __expf(se[p] - mx);
        se[p] = ex;
        sum += ex;
    }
    red[tid] = sum; __syncthreads();
    for (int s = 128; s; s >>= 1) {
        if (tid < s) red[tid] += red[tid + s];
        __syncthreads();
    }
    sum = red[0]; __syncthreads();

    const float inv = 1.f / sum;
    float* out_alpha = out + Bn * Cn;
    float* out_asum  = out + Bn * Cn + Bn * HWn;
    #pragma unroll
    for (int i = 0; i < 16; i++) {
        int p = i * 256 + tid;
        float al = se[p] * inv;
        g_alpha[b * HWn + p] = al;
        out_alpha[b * HWn + p] = al;
        out_asum[b * HWn + p] = al + asum[b * HWn + p];
    }
}

// ---------------- context ----------------
__global__ void k_context(const float* __restrict__ cnn,
                          float* __restrict__ out) {
    const int c = blockIdx.x, b = blockIdx.y, tid = threadIdx.x;
    const float4* row = (const float4*)(cnn + ((size_t)b * Cn + c) * HWn);
    const float4* al  = (const float4*)(g_alpha + b * HWn);
    float s = 0.f;
    #pragma unroll
    for (int it = 0; it < 4; it++) {
        int p = it * 256 + tid;
        float4 r = row[p], a = al[p];
        s = fmaf(a.x, r.x, s); s = fmaf(a.y, r.y, s);
        s = fmaf(a.z, r.z, s); s = fmaf(a.w, r.w, s);
    }
    #pragma unroll
    for (int off = 16; off; off >>= 1)
        s += __shfl_xor_sync(0xffffffffu, s, off);
    __shared__ float red[8];
    if ((tid & 31) == 0) red[tid >> 5] = s;
    __syncthreads();
    if (tid == 0) {
        float t = red[0] + red[1] + red[2] + red[3]
                + red[4] + red[5] + red[6] + red[7];
        out[b * Cn + c] = t;
    }
}

typedef CUresult (*PFN_encodeTiled)(
    CUtensorMap*, CUtensorMapDataType, cuuint32_t, void*,
    const cuuint64_t*, const cuuint64_t*, const cuuint32_t*, const cuuint32_t*,
    CUtensorMapInterleave, CUtensorMapSwizzle, CUtensorMapL2promotion, CUtensorMapFloatOOBfill);

extern "C" void kernel_launch(void* const* d_in, const int* in_sizes, int n_in,
                              void* d_out, int out_size) {
    const float* cnn     = (const float*)d_in[0];   // [16,684,32,128]
    const float* cft     = (const float*)d_in[1];   // [16,512,32,128]
    const float* hidden  = (const float*)d_in[2];   // [16,256]
    const float* asum    = (const float*)d_in[3];   // [16,1,32,128]
    const int*   mask    = (const int*)  d_in[4];   // [16,1,32,128]
    const float* cmt     = (const float*)d_in[5];   // [16,32,128,512]
    const float* Wh      = (const float*)d_in[6];   // [512,256]
    const float* bh      = (const float*)d_in[7];   // [512]
    const float* Wconv   = (const float*)d_in[8];   // [512,1,11,11]
    const float* Wattn   = (const float*)d_in[9];   // [512,512]
    const float* Walpha  = (const float*)d_in[10];  // [1,512]
    // d_in[11] = b_alpha: softmax-invariant, skipped

    float* out = (float*)d_out; // [ context 16*684 | alpha 16*4096 | alpha_sum_new 16*4096 ]

    // ---- build tensormaps (host CPU work at capture; no allocation) ----
    void* fn = nullptr;
    cudaDriverEntryPointQueryResult qr;
    cudaGetDriverEntryPoint("cuTensorMapEncodeTiled", &fn, cudaEnableDefault, &qr);
    PFN_encodeTiled enc = (PFN_encodeTiled)fn;

    void* wptr = nullptr;
    cudaGetSymbolAddress(&wptr, g_weffb);

    CUtensorMap tmCF, tmCM, tmW;
    {   // cft as [w=128][h=32][b*A=8192] f32, box {32,1,16}, SW128
        cuuint64_t d[3]  = {128, 32, 8192};
        cuuint64_t s[2]  = {512, 16384};
        cuuint32_t bx[3] = {32, 1, 16};
        cuuint32_t es[3] = {1, 1, 1};
        enc(&tmCF, CU_TENSOR_MAP_DATA_TYPE_FLOAT32, 3, (void*)cft, d, s, bx, es,
            CU_TENSOR_MAP_INTERLEAVE_NONE, CU_TENSOR_MAP_SWIZZLE_128B,
            CU_TENSOR_MAP_L2_PROMOTION_L2_128B, CU_TENSOR_MAP_FLOAT_OOB_FILL_NONE);
    }
    {   // cmt as [A=512][b*h*w=65536] f32, box {16,128}, SW64
        cuuint64_t d[2]  = {512, 65536};
        cuuint64_t s[1]  = {2048};
        cuuint32_t bx[2] = {16, 128};
        cuuint32_t es[2] = {1, 1};
        enc(&tmCM, CU_TENSOR_MAP_DATA_TYPE_FLOAT32, 2, (void*)cmt, d, s, bx, es,
            CU_TENSOR_MAP_INTERLEAVE_NONE, CU_TENSOR_MAP_SWIZZLE_64B,
            CU_TENSOR_MAP_L2_PROMOTION_L2_128B, CU_TENSOR_MAP_FLOAT_OOB_FILL_NONE);
    }
    {   // g_weffb as [64 u32][512 a], box {32,16}, SW128
        cuuint64_t d[2]  = {64, 512};
        cuuint64_t s[1]  = {256};
        cuuint32_t bx[2] = {32, 16};
        cuuint32_t es[2] = {1, 1};
        enc(&tmW, CU_TENSOR_MAP_DATA_TYPE_UINT32, 2, wptr, d, s, bx, es,
            CU_TENSOR_MAP_INTERLEAVE_NONE, CU_TENSOR_MAP_SWIZZLE_128B,
            CU_TENSOR_MAP_L2_PROMOTION_L2_128B, CU_TENSOR_MAP_FLOAT_OOB_FILL_NONE);
    }

    cudaFuncSetAttribute(k_energy, cudaFuncAttributeMaxDynamicSharedMemorySize, SM_TOT);

    k_prep<<<656, 256>>>(hidden, Wh, bh, Wattn, Wconv, asum);
    k_energy<<<dim3(2, Hn, Bn), 256, SM_TOT>>>(tmCF, tmCM, tmW, Walpha, asum, mask, out);
    k_context<<<dim3(Cn, Bn), 256>>>(cnn, out);
}

// round 17
// speedup vs baseline: 1.4630x; 1.2138x over previous
#include <cuda_runtime.h>
#include <cuda.h>
#include <cuda_bf16.h>
#include <math.h>
#include <math_constants.h>
#include <cstdint>

#define Bn  16
#define Cn  684
#define Hn  32
#define Wn  128
#define HIDn 256
#define An  512
#define HWn 4096
#define NTAP 121

// ---- scratch (device globals; no allocation allowed) ----
__device__ float    g_query[Bn * An];                      // [b][a]
__device__ __align__(1024) uint32_t g_weffb[An * 64];      // bf16x2 pairs: [a][tap-pair]
__device__ uint16_t g_X[(size_t)Bn * Hn * 128 * 136];      // im2col, padded rows (LDX=136)
__device__ float    g_epart[2 * Bn * HWn];                 // [half][b][pos]
__device__ float    g_alpha[Bn * HWn];
__device__ int      g_cnt[Bn];                             // per-batch completion counters

// k_energy SMEM layout (bytes) — TMA triple-buffered.  NO static shared in k_energy:
// dynamic base must stay 128-aligned for SW128 TMA destinations.
#define LDX 136
#define SM_X   0         // 34816
#define SM_W   34816     // 3 * 4096  (two SW128 sub-tiles of 2048 each)
#define SM_CF  47104     // 3 * 8192  (4 SW128 sub-tiles of 2048)
#define SM_CM  71680     // 3 * 8192  (SW64, 128 rows x 64B)
#define SM_QWA 96256     // 2048
#define SM_MB  98304     // 3 mbarriers (24B) + slast flag @ +24
#define SM_TOT 98368

#define STAGE_BYTES 20480u   // 4096 (W) + 8192 (CF) + 8192 (CM)

#define SWZ128(x) ((x) ^ (((x) >> 3) & 0x70))
#define SWZ64(x)  ((x) ^ (((x) >> 3) & 0x30))

__device__ __forceinline__ float fast_tanh(float x) {
    float y;
    asm("tanh.approx.f32 %0, %1;" : "=f"(y) : "f"(x));
    return y;
}
__device__ __forceinline__ uint32_t smem_u32(const void* p) {
    uint32_t a;
    asm("{ .reg .u64 t; cvta.to.shared.u64 t, %1; cvt.u32.u64 %0, t; }" : "=r"(a) : "l"(p));
    return a;
}
__device__ __forceinline__ void mbar_wait(uint32_t mb, uint32_t ph) {
    asm volatile(
        "{ .reg .pred P; \n"
        "W%=: mbarrier.try_wait.parity.acquire.cta.shared::cta.b64 P, [%0], %1, 0x989680;\n"
        "@P bra.uni D%=; bra.uni W%=; D%=: }"
        :: "r"(mb), "r"(ph) : "memory");
}

// ---------------- fused prep: query (0-15) + weff (16-143) + im2col (144-655) ----------------
// static SMEM kept at 8 KB so ALL branches run at high occupancy.
__global__ void k_prep(const float* __restrict__ hidden,
                       const float* __restrict__ Wh,
                       const float* __restrict__ bh,
                       const float* __restrict__ Wattn,
                       const float* __restrict__ Wconv,
                       const float* __restrict__ asum) {
    __shared__ float sbuf[2048];   // 8 KB, shared by all branches
    const int tid = threadIdx.x;

    if (blockIdx.x == 0 && tid < Bn) g_cnt[tid] = 0;   // reset tail counters each replay

    if (blockIdx.x < 16) {
        // ---- query = hidden @ Wh^T + bh : warp-per-row, COALESCED k-stride loads ----
        const int b = blockIdx.x;
        if (tid < HIDn) sbuf[tid] = hidden[b * HIDn + tid];
        __syncthreads();
        const int warp = tid >> 5, lane = tid & 31;
        for (int a = warp; a < An; a += 8) {
            const float* w = Wh + (size_t)a * HIDn;
            float s = 0.f;
            #pragma unroll
            for (int k = 0; k < HIDn; k += 32)
                s = fmaf(w[k + lane], sbuf[k + lane], s);
            #pragma unroll
            for (int off = 16; off; off >>= 1)
                s += __shfl_xor_sync(0xffffffffu, s, off);
            if (lane == 0) g_query[b * An + a] = s + bh[a];
        }
    } else if (blockIdx.x < 144) {
        // ---- Weff[a][tap] = sum_k Wattn[a][k]*Wconv[k][tap] -> bf16 pairs ----
        const int chunk = blockIdx.x - 16;   // 0..127, 4 a-rows each
        for (int i = tid; i < 4 * 512; i += 256)
            sbuf[i] = Wattn[(size_t)chunk * 4 * 512 + i];
        __syncthreads();
        const int al = tid >> 6, pr = tid & 63;
        float v0 = 0.f, v1 = 0.f;
        const int t0 = pr * 2, t1 = pr * 2 + 1;
        if (t0 < NTAP) {
            #pragma unroll 8
            for (int k = 0; k < 512; k++)
                v0 = fmaf(sbuf[al * 512 + k], __ldg(&Wconv[(size_t)k * NTAP + t0]), v0);
        }
        if (t1 < NTAP) {
            #pragma unroll 8
            for (int k = 0; k < 512; k++)
                v1 = fmaf(sbuf[al * 512 + k], __ldg(&Wconv[(size_t)k * NTAP + t1]), v1);
        }
        uint32_t lo = (uint32_t)__bfloat16_as_ushort(__float2bfloat16(v0));
        uint32_t hi = (uint32_t)__bfloat16_as_ushort(__float2bfloat16(v1));
        g_weffb[(chunk * 4 + al) * 64 + pr] = lo | (hi << 16);
    } else {
        // ---- im2col via SMEM halo window (coalesced loads, LDS-fed taps) ----
        const int idx = blockIdx.x - 144;    // 0..511
        const int h = idx % Hn, b = idx / Hn;
        const float* arow = asum + (size_t)b * HWn;
        float (*win)[144] = (float(*)[144])sbuf;   // 11 x 144 = 1584 floats

        for (int i = tid; i < 11 * 144; i += 256) {
            int r = i / 144, c = i % 144;
            int gh = h - 5 + r, gw = c - 5;
            float v = 0.f;
            if (gh >= 0 && gh < Hn && gw >= 0 && gw < Wn)
                v = arow[gh * Wn + gw];
            win[r][c] = v;
        }
        __syncthreads();

        uint32_t* dst = (uint32_t*)(g_X + ((size_t)(b * Hn + h)) * 128 * LDX);
        for (int o = tid; o < 128 * 64; o += 256) {
            int mm = o >> 6, pr = o & 63;
            uint32_t packed = 0;
            #pragma unroll
            for (int hf = 0; hf < 2; hf++) {
                int k = pr * 2 + hf;
                float v = 0.f;
                if (k < NTAP) {
                    int i = k / 11, j = k % 11;
                    v = win[i][mm + j];
                }
                packed |= ((uint32_t)__bfloat16_as_ushort(__float2bfloat16(v))) << (16 * hf);
            }
            dst[mm * (LDX / 2) + pr] = packed;
        }
    }
}

// ---------------- energy: mma.sync + TMA-staged operands + softmax tail ----------------
// grid (2 a-halves, H, B), 256 threads (8 warps). Warp wid owns positions [16*wid, 16*wid+16).
__global__ void __launch_bounds__(256, 2) k_energy(
    const __grid_constant__ CUtensorMap tmCF,
    const __grid_constant__ CUtensorMap tmCM,
    const __grid_constant__ CUtensorMap tmW,
    const float* __restrict__ walpha,
    const float* __restrict__ asum,
    const int*   __restrict__ mask,
    float* __restrict__ out)
{
    extern __shared__ char smem[];
    const uint32_t sb = smem_u32(smem);
    const int half = blockIdx.x, h = blockIdx.y, b = blockIdx.z;
    const int tid = threadIdx.x, wid = tid >> 5, lane = tid & 31;
    const int g = lane >> 2, tig = lane & 3;

    // ---- stage X (plain copy) + QWA ----
    {
        const uint4* src = (const uint4*)(g_X + ((size_t)(b * Hn + h)) * 128 * LDX);
        uint4* dst = (uint4*)(smem + SM_X);
        #pragma unroll
        for (int o = tid; o < 2176; o += 256) dst[o] = src[o];
    }
    float2* QWA = (float2*)(smem + SM_QWA);
    QWA[tid] = make_float2(g_query[b * An + half * 256 + tid], walpha[half * 256 + tid]);

    if (tid == 0) {
        #pragma unroll
        for (int s = 0; s < 3; s++)
            asm volatile("mbarrier.init.shared.b64 [%0], %1;" :: "r"(sb + SM_MB + s * 8), "r"(1u) : "memory");
    }
    __syncthreads();

    // one-thread TMA stage of tile 'it' into buffer 'slot'
    auto stage = [&](int slot, int it) {
        const uint32_t mb = sb + SM_MB + slot * 8;
        const int a0 = half * 256 + it * 16;
        asm volatile("mbarrier.arrive.expect_tx.shared.b64 _, [%0], %1;" :: "r"(mb), "r"(STAGE_BYTES) : "memory");
        #pragma unroll
        for (int s = 0; s < 2; s++)
            asm volatile("cp.async.bulk.tensor.2d.shared::cta.global.tile.mbarrier::complete_tx::bytes "
                         "[%0], [%1, {%2, %3}], [%4];"
                         :: "r"(sb + SM_W + slot * 4096 + s * 2048), "l"(&tmW),
                            "r"(s * 32), "r"(a0), "r"(mb) : "memory");
        #pragma unroll
        for (int s = 0; s < 4; s++)
            asm volatile("cp.async.bulk.tensor.3d.shared::cta.global.tile.mbarrier::complete_tx::bytes "
                         "[%0], [%1, {%2, %3, %4}], [%5];"
                         :: "r"(sb + SM_CF + slot * 8192 + s * 2048), "l"(&tmCF),
                            "r"(s * 32), "r"(h), "r"(b * 512 + a0), "r"(mb) : "memory");
        asm volatile("cp.async.bulk.tensor.2d.shared::cta.global.tile.mbarrier::complete_tx::bytes "
                     "[%0], [%1, {%2, %3}], [%4];"
                     :: "r"(sb + SM_CM + slot * 8192), "l"(&tmCM),
                        "r"(a0), "r"((b * Hn + h) * 128), "r"(mb) : "memory");
    };

    if (tid == 0) { stage(0, 0); stage(1, 1); }

    // ---- persistent X fragments (both n-halves) ----
    const int pos0 = wid * 16;
    uint32_t bf[2][8][2];
    #pragma unroll
    for (int nh = 0; nh < 2; nh++) {
        const char* xrow = smem + SM_X + (pos0 + nh * 8 + g) * (LDX * 2);
        #pragma unroll
        for (int kk = 0; kk < 8; kk++) {
            bf[nh][kk][0] = *(const uint32_t*)(xrow + (kk * 16 + tig * 2) * 2);
            bf[nh][kk][1] = *(const uint32_t*)(xrow + (kk * 16 + tig * 2 + 8) * 2);
        }
    }

    float epos[4] = {0.f, 0.f, 0.f, 0.f};
    const int p0 = pos0 + tig * 2;
    const int st = p0 >> 5, pl = p0 & 31;

    #pragma unroll
    for (int mt = 0; mt < 16; mt++) {
        const int slot = mt % 3;
        const uint32_t ph = (uint32_t)((mt / 3) & 1);

        mbar_wait(sb + SM_MB + slot * 8, ph);
        __syncthreads();

        if (tid == 0 && mt < 14) stage((mt + 2) % 3, mt + 2);

        // ---- GEMM ----
        const uint32_t wb = sb + SM_W + slot * 4096;
        const uint32_t wlane = (uint32_t)((lane & 15) * 128 + (lane >> 4) * 16);
        float c0[4] = {0.f, 0.f, 0.f, 0.f};
        float c1[4] = {0.f, 0.f, 0.f, 0.f};
        #pragma unroll
        for (int kk = 0; kk < 8; kk++) {
            uint32_t a0r, a1r, a2r, a3r;
            uint32_t addr = wb + (kk >> 2) * 2048 + SWZ128(wlane + (kk & 3) * 32);
            asm volatile("ldmatrix.sync.aligned.m8n8.x4.shared.b16 {%0,%1,%2,%3}, [%4];"
                         : "=r"(a0r), "=r"(a1r), "=r"(a2r), "=r"(a3r) : "r"(addr));
            asm volatile("mma.sync.aligned.m16n8k16.row.col.f32.bf16.bf16.f32 "
                         "{%0,%1,%2,%3}, {%4,%5,%6,%7}, {%8,%9}, {%0,%1,%2,%3};"
                         : "+f"(c0[0]), "+f"(c0[1]), "+f"(c0[2]), "+f"(c0[3])
                         : "r"(a0r), "r"(a1r), "r"(a2r), "r"(a3r),
                           "r"(bf[0][kk][0]), "r"(bf[0][kk][1]));
            asm volatile("mma.sync.aligned.m16n8k16.row.col.f32.bf16.bf16.f32 "
                         "{%0,%1,%2,%3}, {%4,%5,%6,%7}, {%8,%9}, {%0,%1,%2,%3};"
                         : "+f"(c1[0]), "+f"(c1[1]), "+f"(c1[2]), "+f"(c1[3])
                         : "r"(a0r), "r"(a1r), "r"(a2r), "r"(a3r),
                           "r"(bf[1][kk][0]), "r"(bf[1][kk][1]));
        }

        // ---- epilogue ----
        const char* cfp = smem + SM_CF + slot * 8192 + st * 2048;
        const char* cmp = smem + SM_CM + slot * 8192;
        const int A0l = mt * 16;
        const float2 qw0 = QWA[A0l + g], qw1 = QWA[A0l + g + 8];

        float2 cf00 = *(const float2*)(cfp + SWZ128(g * 128 + pl * 4));
        float2 cf01 = *(const float2*)(cfp + SWZ128((g + 8) * 128 + pl * 4));
        float2 cf10 = *(const float2*)(cfp + SWZ128(g * 128 + (pl + 8) * 4));
        float2 cf11 = *(const float2*)(cfp + SWZ128((g + 8) * 128 + (pl + 8) * 4));

        float cm00a = *(const float*)(cmp + SWZ64(p0 * 64 + g * 4));
        float cm00b = *(const float*)(cmp + SWZ64((p0 + 1) * 64 + g * 4));
        float cm01a = *(const float*)(cmp + SWZ64(p0 * 64 + g * 4 + 32));
        float cm01b = *(const float*)(cmp + SWZ64((p0 + 1) * 64 + g * 4 + 32));
        float cm10a = *(const float*)(cmp + SWZ64((p0 + 8) * 64 + g * 4));
        float cm10b = *(const float*)(cmp + SWZ64((p0 + 9) * 64 + g * 4));
        float cm11a = *(const float*)(cmp + SWZ64((p0 + 8) * 64 + g * 4 + 32));
        float cm11b = *(const float*)(cmp + SWZ64((p0 + 9) * 64 + g * 4 + 32));

        float s;
        s = c0[0] + cf00.x + cm00a + qw0.x; epos[0] = fmaf(qw0.y, fast_tanh(s), epos[0]);
        s = c0[1] + cf00.y + cm00b + qw0.x; epos[1] = fmaf(qw0.y, fast_tanh(s), epos[1]);
        s = c0[2] + cf01.x + cm01a + qw1.x; epos[0] = fmaf(qw1.y, fast_tanh(s), epos[0]);
        s = c0[3] + cf01.y + cm01b + qw1.x; epos[1] = fmaf(qw1.y, fast_tanh(s), epos[1]);
        s = c1[0] + cf10.x + cm10a + qw0.x; epos[2] = fmaf(qw0.y, fast_tanh(s), epos[2]);
        s = c1[1] + cf10.y + cm10b + qw0.x; epos[3] = fmaf(qw0.y, fast_tanh(s), epos[3]);
        s = c1[2] + cf11.x + cm11a + qw1.x; epos[2] = fmaf(qw1.y, fast_tanh(s), epos[2]);
        s = c1[3] + cf11.y + cm11b + qw1.x; epos[3] = fmaf(qw1.y, fast_tanh(s), epos[3]);
    }

    // reduce over the 8 g-lanes (lane bits 2-4)
    #pragma unroll
    for (int j = 0; j < 4; j++) {
        epos[j] += __shfl_xor_sync(0xffffffffu, epos[j], 4);
        epos[j] += __shfl_xor_sync(0xffffffffu, epos[j], 8);
        epos[j] += __shfl_xor_sync(0xffffffffu, epos[j], 16);
    }
    if (lane < 4) {
        float* ep = g_epart + ((size_t)half * Bn + b) * HWn + h * Wn + pos0;
        ep[tig * 2]         = epos[0];
        ep[tig * 2 + 1]     = epos[1];
        ep[8 + tig * 2]     = epos[2];
        ep[8 + tig * 2 + 1] = epos[3];
    }

    // ---- softmax tail: last block per batch (threadFenceReduction pattern) ----
    // slast flag lives in DYNAMIC smem (no static shared -> TMA dsts stay 128-aligned)
    int* slastp = (int*)(smem + SM_MB + 24);
    __threadfence();
    __syncthreads();            // all epart stores issued before the arrival
    if (tid == 0) {
        int old = atomicAdd(&g_cnt[b], 1);
        *slastp = (old == 2 * Hn - 1);
    }
    __syncthreads();
    if (*slastp == 0) return;

    // this block: deterministic per-batch softmax over 4096 positions
    float* se  = (float*)smem;            // 16 KB (X region, no longer needed)
    float* red = (float*)(smem + 16384);  // 1 KB

    float mx = -CUDART_INF_F;
    #pragma unroll
    for (int i = 0; i < 16; i++) {
        int p = i * 256 + tid;
        float e = g_epart[b * HWn + p] + g_epart[(Bn + b) * HWn + p];
        if (mask[b * HWn + p] == 0) e = -CUDART_INF_F;
        se[p] = e;
        mx = fmaxf(mx, e);
    }
    red[tid] = mx; __syncthreads();
    for (int s = 128; s; s >>= 1) {
        if (tid < s) red[tid] = fmaxf(red[tid], red[tid + s]);
        __syncthreads();
    }
    mx = red[0]; __syncthreads();

    float sum = 0.f;
    #pragma unroll
    for (int i = 0; i < 16; i++) {
        int p = i * 256 + tid;
        float ex = __expf(se[p] - mx);
        se[p] = ex;
        sum += ex;
    }
    red[tid] = sum; __syncthreads();
    for (int s = 128; s; s >>= 1) {
        if (tid < s) red[tid] += red[tid + s];
        __syncthreads();
    }
    sum = red[0]; __syncthreads();

    const float inv = 1.f / sum;
    float* out_alpha = out + Bn * Cn;
    float* out_asum  = out + Bn * Cn + Bn * HWn;
    #pragma unroll
    for (int i = 0; i < 16; i++) {
        int p = i * 256 + tid;
        float al = se[p] * inv;
        g_alpha[b * HWn + p] = al;
        out_alpha[b * HWn + p] = al;
        out_asum[b * HWn + p] = al + asum[b * HWn + p];
    }
}

// ---------------- context ----------------
__global__ void k_context(const float* __restrict__ cnn,
                          float* __restrict__ out) {
    const int c = blockIdx.x, b = blockIdx.y, tid = threadIdx.x;
    const float4* row = (const float4*)(cnn + ((size_t)b * Cn + c) * HWn);
    const float4* al  = (const float4*)(g_alpha + b * HWn);
    float s = 0.f;
    #pragma unroll
    for (int it = 0; it < 4; it++) {
        int p = it * 256 + tid;
        float4 r = row[p], a = al[p];
        s = fmaf(a.x, r.x, s); s = fmaf(a.y, r.y, s);
        s = fmaf(a.z, r.z, s); s = fmaf(a.w, r.w, s);
    }
    #pragma unroll
    for (int off = 16; off; off >>= 1)
        s += __shfl_xor_sync(0xffffffffu, s, off);
    __shared__ float red[8];
    if ((tid & 31) == 0) red[tid >> 5] = s;
    __syncthreads();
    if (tid == 0) {
        float t = red[0] + red[1] + red[2] + red[3]
                + red[4] + red[5] + red[6] + red[7];
        out[b * Cn + c] = t;
    }
}

typedef CUresult (*PFN_encodeTiled)(
    CUtensorMap*, CUtensorMapDataType, cuuint32_t, void*,
    const cuuint64_t*, const cuuint64_t*, const cuuint32_t*, const cuuint32_t*,
    CUtensorMapInterleave, CUtensorMapSwizzle, CUtensorMapL2promotion, CUtensorMapFloatOOBfill);

extern "C" void kernel_launch(void* const* d_in, const int* in_sizes, int n_in,
                              void* d_out, int out_size) {
    const float* cnn     = (const float*)d_in[0];   // [16,684,32,128]
    const float* cft     = (const float*)d_in[1];   // [16,512,32,128]
    const float* hidden  = (const float*)d_in[2];   // [16,256]
    const float* asum    = (const float*)d_in[3];   // [16,1,32,128]
    const int*   mask    = (const int*)  d_in[4];   // [16,1,32,128]
    const float* cmt     = (const float*)d_in[5];   // [16,32,128,512]
    const float* Wh      = (const float*)d_in[6];   // [512,256]
    const float* bh      = (const float*)d_in[7];   // [512]
    const float* Wconv   = (const float*)d_in[8];   // [512,1,11,11]
    const float* Wattn   = (const float*)d_in[9];   // [512,512]
    const float* Walpha  = (const float*)d_in[10];  // [1,512]
    // d_in[11] = b_alpha: softmax-invariant, skipped

    float* out = (float*)d_out; // [ context 16*684 | alpha 16*4096 | alpha_sum_new 16*4096 ]

    // ---- build tensormaps (host CPU work at capture; no allocation) ----
    void* fn = nullptr;
    cudaDriverEntryPointQueryResult qr;
    cudaGetDriverEntryPoint("cuTensorMapEncodeTiled", &fn, cudaEnableDefault, &qr);
    PFN_encodeTiled enc = (PFN_encodeTiled)fn;

    void* wptr = nullptr;
    cudaGetSymbolAddress(&wptr, g_weffb);

    CUtensorMap tmCF, tmCM, tmW;
    {   // cft as [w=128][h=32][b*A=8192] f32, box {32,1,16}, SW128
        cuuint64_t d[3]  = {128, 32, 8192};
        cuuint64_t s[2]  = {512, 16384};
        cuuint32_t bx[3] = {32, 1, 16};
        cuuint32_t es[3] = {1, 1, 1};
        enc(&tmCF, CU_TENSOR_MAP_DATA_TYPE_FLOAT32, 3, (void*)cft, d, s, bx, es,
            CU_TENSOR_MAP_INTERLEAVE_NONE, CU_TENSOR_MAP_SWIZZLE_128B,
            CU_TENSOR_MAP_L2_PROMOTION_L2_128B, CU_TENSOR_MAP_FLOAT_OOB_FILL_NONE);
    }
    {   // cmt as [A=512][b*h*w=65536] f32, box {16,128}, SW64
        cuuint64_t d[2]  = {512, 65536};
        cuuint64_t s[1]  = {2048};
        cuuint32_t bx[2] = {16, 128};
        cuuint32_t es[2] = {1, 1};
        enc(&tmCM, CU_TENSOR_MAP_DATA_TYPE_FLOAT32, 2, (void*)cmt, d, s, bx, es,
            CU_TENSOR_MAP_INTERLEAVE_NONE, CU_TENSOR_MAP_SWIZZLE_64B,
            CU_TENSOR_MAP_L2_PROMOTION_L2_128B, CU_TENSOR_MAP_FLOAT_OOB_FILL_NONE);
    }
    {   // g_weffb as [64 u32][512 a], box {32,16}, SW128
        cuuint64_t d[2]  = {64, 512};
        cuuint64_t s[1]  = {256};
        cuuint32_t bx[2] = {32, 16};
        cuuint32_t es[2] = {1, 1};
        enc(&tmW, CU_TENSOR_MAP_DATA_TYPE_UINT32, 2, wptr, d, s, bx, es,
            CU_TENSOR_MAP_INTERLEAVE_NONE, CU_TENSOR_MAP_SWIZZLE_128B,
            CU_TENSOR_MAP_L2_PROMOTION_L2_128B, CU_TENSOR_MAP_FLOAT_OOB_FILL_NONE);
    }

    cudaFuncSetAttribute(k_energy, cudaFuncAttributeMaxDynamicSharedMemorySize, SM_TOT);

    k_prep<<<656, 256>>>(hidden, Wh, bh, Wattn, Wconv, asum);
    k_energy<<<dim3(2, Hn, Bn), 256, SM_TOT>>>(tmCF, tmCM, tmW, Walpha, asum, mask, out);
    k_context<<<dim3(Cn, Bn), 256>>>(cnn, out);
}